// round 1
// baseline (speedup 1.0000x reference)
#include <cuda_runtime.h>
#include <math.h>

// Problem constants
#define DIMC   64
#define HEADS  8
#define WINS   4
#define LTOK   36
#define DHD    8
#define BB     8
#define HH     256
#define WW     256
#define WSZ    128

// Scratch: dynamic conv weights, layout [win][ci][co][12] (taps 0..8 used, 9..11 pad)
__device__ __align__(16) float g_weights[WINS * 64 * 64 * 12];

// ===========================================================================
// Kernel A: build dynamic conv kernels (attention over 36 tokens + SE gate)
// one block per o (attention batch dim == conv output channel), 288 threads
// ===========================================================================
__global__ void __launch_bounds__(288) gen_kernels(
    const float* __restrict__ conv_w,  // (4,64,64,3,3)
    const float* __restrict__ w_qkv,   // (192,64)
    const float* __restrict__ b_qkv,   // (192)
    const float* __restrict__ w_out,   // (64,64)
    const float* __restrict__ b_out,   // (64)
    const float* __restrict__ se_w1,   // (4,4,64)
    const float* __restrict__ se_b1,   // (4,4)
    const float* __restrict__ se_w2,   // (4,64,4)
    const float* __restrict__ se_b2)   // (4,64)
{
    __shared__ float sm_a[LTOK * 64];       // kern0, later attention output (36x64)
    __shared__ float sm_qkv[LTOK * 192];    // (36,192)
    __shared__ float sm_k1[LTOK * 64];      // projected kernels (36,64)
    __shared__ float sm_pooled[64];
    __shared__ float sm_h1[4];

    const int o = blockIdx.x;
    const int t = threadIdx.x;

    // ---- Phase 1: kern0[l][i] = conv_w[w][o][i][p], l = w*9+p
    for (int idx = t; idx < LTOK * 64; idx += 288) {
        int l = idx >> 6, i = idx & 63;
        int w_ = l / 9, p = l - w_ * 9;
        sm_a[idx] = conv_w[(((w_ * 64 + o) * 64 + i) * 9) + p];
    }
    __syncthreads();

    // ---- Phase 2: qkv[l][j] = kern0[l][:] . w_qkv[j][:] + b_qkv[j]
    if (t < 192) {
        float wrow[64];
#pragma unroll
        for (int i = 0; i < 64; i++) wrow[i] = w_qkv[t * 64 + i];
        const float bj = b_qkv[t];
        for (int l = 0; l < LTOK; l++) {
            float acc = bj;
#pragma unroll
            for (int i = 0; i < 64; i++) acc += sm_a[l * 64 + i] * wrow[i];
            sm_qkv[l * 192 + t] = acc;
        }
    }
    __syncthreads();

    // ---- Phase 3: attention, one (head,l) per thread; write out to sm_a
    {
        const int h = t / LTOK;        // 0..7
        const int l = t - h * LTOK;    // 0..35
        const float scale = 0.3535533905932738f;  // 8^-0.5
        float sc[LTOK];
        float mx = -1e30f;
#pragma unroll
        for (int m = 0; m < LTOK; m++) {
            float s_ = 0.f;
#pragma unroll
            for (int d = 0; d < DHD; d++)
                s_ += sm_qkv[l * 192 + h * 8 + d] * sm_qkv[m * 192 + 64 + h * 8 + d];
            sc[m] = s_ * scale;
            mx = fmaxf(mx, sc[m]);
        }
        float denom = 0.f;
#pragma unroll
        for (int m = 0; m < LTOK; m++) { sc[m] = expf(sc[m] - mx); denom += sc[m]; }
        const float inv = 1.f / denom;
        float ov[DHD];
#pragma unroll
        for (int d = 0; d < DHD; d++) ov[d] = 0.f;
#pragma unroll
        for (int m = 0; m < LTOK; m++) {
            const float p_ = sc[m];
#pragma unroll
            for (int d = 0; d < DHD; d++)
                ov[d] += p_ * sm_qkv[m * 192 + 128 + h * 8 + d];
        }
#pragma unroll
        for (int d = 0; d < DHD; d++)
            sm_a[l * 64 + h * 8 + d] = ov[d] * inv;
    }
    __syncthreads();

    // ---- Phase 4: output projection: k1[l][c] = attn_out[l][:] . w_out[c][:] + b_out[c]
    if (t < 64) {
        const float bj = b_out[t];
        for (int l = 0; l < LTOK; l++) {
            float acc = bj;
#pragma unroll
            for (int c = 0; c < 64; c++) acc += sm_a[l * 64 + c] * w_out[t * 64 + c];
            sm_k1[l * 64 + t] = acc;
        }
    }
    __syncthreads();

    // ---- Phase 5: SE gate per window, then write scaled weights to scratch
    for (int w_ = 0; w_ < WINS; w_++) {
        if (t < 64) {
            float pl = 0.f;
#pragma unroll
            for (int p = 0; p < 9; p++) pl += sm_k1[(w_ * 9 + p) * 64 + t];
            sm_pooled[t] = pl * (1.f / 9.f);
        }
        __syncthreads();
        if (t < 4) {
            float a = se_b1[w_ * 4 + t];
            for (int i = 0; i < 64; i++)
                a += sm_pooled[i] * se_w1[(w_ * 4 + t) * 64 + i];
            sm_h1[t] = fmaxf(a, 0.f);
        }
        __syncthreads();
        if (t < 64) {
            float z = se_b2[w_ * 64 + t];
#pragma unroll
            for (int r = 0; r < 4; r++) z += sm_h1[r] * se_w2[(w_ * 64 + t) * 4 + r];
            const float s_ = 1.f / (1.f + expf(-z));
            // kfinal[w][o][i][p] = k1[w*9+p][i] * s(w,o,i); scratch layout [w][i][o][12]
#pragma unroll
            for (int p = 0; p < 9; p++)
                g_weights[((w_ * 64 + t) * 64 + o) * 12 + p] =
                    sm_k1[(w_ * 9 + p) * 64 + t] * s_;
        }
        __syncthreads();
    }
}

// ===========================================================================
// Kernel B: fused per-window dynamic conv (3x3, pad 1 per window) + channel
// LayerNorm + residual. One thread = one pixel, all 64 output channels in regs.
// Grid: (64 tiles of 16x16, 4 windows, 8 batch), 256 threads.
// ===========================================================================
#define CI_CHUNK 8

__global__ void __launch_bounds__(256, 2) conv_ln(
    const float* __restrict__ x,
    const float* __restrict__ ln_w,
    const float* __restrict__ ln_b,
    float* __restrict__ out)
{
    __shared__ float  xs[CI_CHUNK][18 * 18];       // halo tile per ci
    __shared__ float4 wsm[CI_CHUNK * 64 * 3];      // [ci][co][3xfloat4]
    __shared__ float  lnw[64], lnb[64];

    const int b   = blockIdx.z;
    const int w_  = blockIdx.y;
    const int tb  = blockIdx.x;
    const int oy0 = (tb >> 3) << 4;
    const int ox0 = (tb & 7) << 4;
    const int base_y = (w_ >> 1) << 7;
    const int base_x = (w_ & 1) << 7;
    const int t  = threadIdx.x;
    const int py = t >> 4, px = t & 15;

    if (t < 64) { lnw[t] = ln_w[t]; lnb[t] = ln_b[t]; }

    float acc[64];
#pragma unroll
    for (int c = 0; c < 64; c++) acc[c] = 0.f;

    for (int c0 = 0; c0 < 64; c0 += CI_CHUNK) {
        __syncthreads();  // previous chunk fully consumed (also covers lnw init)

        // load x halo tile (zero outside the 128x128 window: per-window padding)
        for (int idx = t; idx < CI_CHUNK * 324; idx += 256) {
            int ci = idx / 324; int rr = idx - ci * 324;
            int yy = rr / 18, xx = rr - yy * 18;
            int ly = oy0 + yy - 1, lx = ox0 + xx - 1;
            float v = 0.f;
            if ((unsigned)ly < 128u && (unsigned)lx < 128u)
                v = x[((b * 64 + c0 + ci) * 256 + (base_y + ly)) * 256 + (base_x + lx)];
            xs[ci][rr] = v;
        }
        // load weight chunk
        const float4* gw = (const float4*)&g_weights[((w_ * 64 + c0) * 64) * 12];
        for (int idx = t; idx < CI_CHUNK * 64 * 3; idx += 256)
            wsm[idx] = gw[idx];
        __syncthreads();

#pragma unroll 1
        for (int ci = 0; ci < CI_CHUNK; ci++) {
            float xv[9];
            const float* xp = &xs[ci][py * 18 + px];
#pragma unroll
            for (int ky = 0; ky < 3; ky++)
#pragma unroll
                for (int kx = 0; kx < 3; kx++)
                    xv[ky * 3 + kx] = xp[ky * 18 + kx];
            const float4* wp = &wsm[ci * 64 * 3];
#pragma unroll
            for (int co = 0; co < 64; co++) {
                const float4 w0 = wp[co * 3 + 0];
                const float4 w1 = wp[co * 3 + 1];
                const float4 w2 = wp[co * 3 + 2];
                float a = acc[co];
                a += w0.x * xv[0]; a += w0.y * xv[1]; a += w0.z * xv[2];
                a += w0.w * xv[3]; a += w1.x * xv[4]; a += w1.y * xv[5];
                a += w1.z * xv[6]; a += w1.w * xv[7]; a += w2.x * xv[8];
                acc[co] = a;
            }
        }
    }

    // ---- channel LayerNorm (thread-local over the 64 accumulators) + residual
    float mu = 0.f;
#pragma unroll
    for (int c = 0; c < 64; c++) mu += acc[c];
    mu *= (1.f / 64.f);
    float var = 0.f;
#pragma unroll
    for (int c = 0; c < 64; c++) { const float d = acc[c] - mu; var += d * d; }
    var *= (1.f / 64.f);
    const float inv = rsqrtf(var + 1e-5f);

    const int gy = base_y + oy0 + py;
    const int gx = base_x + ox0 + px;
#pragma unroll
    for (int c = 0; c < 64; c++) {
        const int gidx = ((b * 64 + c) * 256 + gy) * 256 + gx;
        out[gidx] = x[gidx] + (acc[c] - mu) * inv * lnw[c] + lnb[c];
    }
}

// ===========================================================================
extern "C" void kernel_launch(void* const* d_in, const int* in_sizes, int n_in,
                              void* d_out, int out_size)
{
    const float* x      = (const float*)d_in[0];
    const float* conv_w = (const float*)d_in[1];
    const float* w_qkv  = (const float*)d_in[2];
    const float* b_qkv  = (const float*)d_in[3];
    const float* w_out  = (const float*)d_in[4];
    const float* b_out  = (const float*)d_in[5];
    const float* se_w1  = (const float*)d_in[6];
    const float* se_b1  = (const float*)d_in[7];
    const float* se_w2  = (const float*)d_in[8];
    const float* se_b2  = (const float*)d_in[9];
    const float* ln_w   = (const float*)d_in[10];
    const float* ln_b   = (const float*)d_in[11];
    float* out = (float*)d_out;

    gen_kernels<<<64, 288>>>(conv_w, w_qkv, b_qkv, w_out, b_out,
                             se_w1, se_b1, se_w2, se_b2);
    conv_ln<<<dim3(64, 4, 8), 256>>>(x, ln_w, ln_b, out);
}